// round 7
// baseline (speedup 1.0000x reference)
#include <cuda_runtime.h>
#include <cuda_fp16.h>
#include <cstdint>
#include <math.h>

#define BB 128
#define II 512
#define TT 256
#define HH 1024
#define GG (4*HH)

// ---------------- scratch -----------------------------------------------
__device__ float4 g_xproj4[(size_t)TT * BB * GG / 4];       // [t][b][g] fp32
__device__ uint4  g_WhhH4[(size_t)GG * HH / 8];             // fp16 W_hh
__device__ uint4  g_WihH4[(size_t)GG * II / 8];             // fp16 W_ih
__device__ uint4  g_xT4[(size_t)BB * TT * II / 8];          // fp16 x^T [b][t][k]
__device__ uint4  g_hbf4[2][(size_t)BB * HH / 8];           // h fp16, double buffer
__device__ float  g_bias[GG];
__device__ unsigned g_flags[128];                           // grid barrier flags

// ---------------- helpers -----------------------------------------------
__device__ __forceinline__ uint32_t smem_u32(const void* p) {
    uint32_t a;
    asm("{ .reg .u64 t; cvta.to.shared.u64 t, %1; cvt.u32.u64 %0, t; }" : "=r"(a) : "l"(p));
    return a;
}
#define CP16(sa, ga) \
    asm volatile("cp.async.cg.shared.global [%0], [%1], 16;" :: "r"(sa), "l"(ga) : "memory")
#define CP_COMMIT() asm volatile("cp.async.commit_group;" ::: "memory")
#define CP_WAIT2()  asm volatile("cp.async.wait_group 2;" ::: "memory")
#define CP_WAIT1()  asm volatile("cp.async.wait_group 1;" ::: "memory")
#define CP_WAIT0()  asm volatile("cp.async.wait_group 0;" ::: "memory")

#define LDSM4(r, a) \
    asm volatile("ldmatrix.sync.aligned.m8n8.x4.shared.b16 {%0,%1,%2,%3}, [%4];" \
        : "=r"((r)[0]), "=r"((r)[1]), "=r"((r)[2]), "=r"((r)[3]) : "r"(a))
#define LDSM2(r, a) \
    asm volatile("ldmatrix.sync.aligned.m8n8.x2.shared.b16 {%0,%1}, [%2];" \
        : "=r"((r)[0]), "=r"((r)[1]) : "r"(a))
#define MMA(d, a, b) \
    asm volatile("mma.sync.aligned.m16n8k16.row.col.f32.f16.f16.f32 " \
        "{%0,%1,%2,%3}, {%4,%5,%6,%7}, {%8,%9}, {%0,%1,%2,%3};" \
        : "+f"((d)[0]), "+f"((d)[1]), "+f"((d)[2]), "+f"((d)[3]) \
        : "r"((a)[0]), "r"((a)[1]), "r"((a)[2]), "r"((a)[3]), "r"((b)[0]), "r"((b)[1]))

extern __shared__ char smem[];

// ---------------------------------------------------------------------------
// Prep kernels
// ---------------------------------------------------------------------------
__global__ void prep_whh(const float* __restrict__ Whh)
{
    size_t i = (size_t)blockIdx.x * blockDim.x + threadIdx.x;
    if (i < (size_t)GG * HH)
        ((__half*)g_WhhH4)[i] = __float2half_rn(Whh[i]);
    if (i < (size_t)BB * HH)
        ((__half*)g_hbf4[0])[i] = __float2half(0.f);
    if (i < 128)
        g_flags[i] = 0;           // reset barrier flags every launch (replay-safe)
}
__global__ void prep_wih(const float* __restrict__ Wih,
                         const float* __restrict__ bih,
                         const float* __restrict__ bhh)
{
    size_t i = (size_t)blockIdx.x * blockDim.x + threadIdx.x;
    if (i < (size_t)GG * II)
        ((__half*)g_WihH4)[i] = __float2half_rn(Wih[i]);
    if (i < GG)
        g_bias[i] = bih[i] + bhh[i];
}
// transpose: x[b][k][t] -> xT[b][t][k] fp16
__global__ void prep_x(const float* __restrict__ x)
{
    __shared__ float s[32][33];
    const int b = blockIdx.z, k0 = blockIdx.y * 32, t0 = blockIdx.x * 32;
    const int tx = threadIdx.x, ty = threadIdx.y;   // 32 x 8
    const float* xb = x + (size_t)b * II * TT;
#pragma unroll
    for (int i = 0; i < 4; i++)
        s[ty + 8 * i][tx] = xb[(size_t)(k0 + ty + 8 * i) * TT + t0 + tx];
    __syncthreads();
    __half* xh = (__half*)g_xT4;
    const size_t base = (size_t)b * TT * II;
#pragma unroll
    for (int i = 0; i < 4; i++) {
        float v = s[tx][ty + 8 * i];
        xh[base + (size_t)(t0 + ty + 8 * i) * II + k0 + tx] = __float2half_rn(v);
    }
}

// ---------------------------------------------------------------------------
// Phase 1: xproj via HMMA fp16 single-pass (unchanged from R6).
// ---------------------------------------------------------------------------
#define SMX_A(bf) ((bf)*36864)
#define SMX_B(bf) ((bf)*36864 + 18432)
#define SMX_TOT 73728

__global__ __launch_bounds__(256, 2) void xproj_mma(void)
{
    const int tx = threadIdx.x, wid = tx >> 5, lane = tx & 31;
    const int gt = blockIdx.x;
    const int tt = blockIdx.y;
    const int b  = blockIdx.z;
    const uint32_t sb = smem_u32(smem);
    const int wm = wid & 1, wn = wid >> 1;

    const __half* xh = (const __half*)g_xT4 + (size_t)b * TT * II + (size_t)tt * 128 * II;
    const __half* Wh = (const __half*)g_WihH4 + (size_t)gt * 128 * II;

    float acc[4][4][4];
#pragma unroll
    for (int f = 0; f < 4; f++)
#pragma unroll
        for (int q = 0; q < 4; q++)
#pragma unroll
            for (int e = 0; e < 4; e++) acc[f][q][e] = 0.f;

    const int srow = tx >> 3, sseg = tx & 7;

#pragma unroll
    for (int r = 0; r < 4; r++) {
        int row = srow + (r << 5);
        uint32_t d = row * 144 + sseg * 16;
        CP16(sb + SMX_A(0) + d, xh + (size_t)row * II + (sseg << 3));
        CP16(sb + SMX_B(0) + d, Wh + (size_t)row * II + (sseg << 3));
    }
    CP_COMMIT();

    int buf = 0;
    for (int kc = 0; kc < 8; kc++) {
        if (kc < 7) {
            const int k0 = (kc + 1) << 6;
#pragma unroll
            for (int r = 0; r < 4; r++) {
                int row = srow + (r << 5);
                uint32_t d = row * 144 + sseg * 16;
                CP16(sb + SMX_A(buf ^ 1) + d, xh + (size_t)row * II + k0 + (sseg << 3));
                CP16(sb + SMX_B(buf ^ 1) + d, Wh + (size_t)row * II + k0 + (sseg << 3));
            }
            CP_COMMIT();
            CP_WAIT1();
        } else {
            CP_WAIT0();
        }
        __syncthreads();

        const uint32_t aoff = (uint32_t)(((lane & 15) * 72 + ((lane >> 4) << 3)) * 2) + wm * 9216;
        const uint32_t aA = sb + SMX_A(buf) + aoff;
        const uint32_t bB = sb + SMX_B(buf) + wn * 4608
                          + (uint32_t)(((lane & 7) * 72 + (((lane >> 3) & 1) << 3)) * 2);
#pragma unroll
        for (int ks = 0; ks < 4; ks++) {
            uint32_t bh[4][2];
#pragma unroll
            for (int q = 0; q < 4; q++)
                LDSM2(bh[q], bB + q * 1152 + ks * 32);
#pragma unroll
            for (int f = 0; f < 4; f++) {
                uint32_t ah[4];
                LDSM4(ah, aA + f * 2304 + ks * 32);
#pragma unroll
                for (int q = 0; q < 4; q++)
                    MMA(acc[f][q], ah, bh[q]);
            }
        }
        __syncthreads();
        buf ^= 1;
    }

    float* xp = (float*)g_xproj4;
#pragma unroll
    for (int f = 0; f < 4; f++) {
        const int trow = tt * 128 + wm * 64 + f * 16 + (lane >> 2);
#pragma unroll
        for (int q = 0; q < 4; q++) {
            const int g = gt * 128 + wn * 32 + q * 8 + ((lane & 3) << 1);
            float2 bb = *(const float2*)&g_bias[g];
            float2 v0; v0.x = acc[f][q][0] + bb.x; v0.y = acc[f][q][1] + bb.y;
            float2 v1; v1.x = acc[f][q][2] + bb.x; v1.y = acc[f][q][3] + bb.y;
            *(float2*)&xp[((size_t)trow * BB + b) * GG + g]       = v0;
            *(float2*)&xp[((size_t)(trow + 8) * BB + b) * GG + g] = v1;
        }
    }
}

// ---------------------------------------------------------------------------
// Flag-array grid barrier: release own flag, poll all 128.
// ---------------------------------------------------------------------------
__device__ __forceinline__ void grid_barrier(int j, int tx, unsigned gen)
{
    __syncthreads();
    if (tx == 0) {
        __threadfence();
        *((volatile unsigned*)&g_flags[j]) = gen;
    }
    if (tx < 128) {
        while (*((volatile unsigned*)&g_flags[tx]) < gen) { }
        __threadfence();
    }
    __syncthreads();
}

// ---------------------------------------------------------------------------
// Phase 2: persistent HMMA recurrent kernel, fp16 single-pass,
// 4-stage cp.async pipeline (1 syncthreads per k-tile), flag barrier.
// CTA j owns h cols [8j,8j+8) => 32 gate cols g = q*1024 + 8j + nn.
// ---------------------------------------------------------------------------
#define SM_WHI 0
#define SM_A(s) (66048 + (s)*18432)
#define SM_TOT (66048 + 4*18432)

__global__ __launch_bounds__(256, 1) void lstm_mma_kernel(float* __restrict__ out)
{
    const int tx   = threadIdx.x;
    const int wid  = tx >> 5;
    const int lane = tx & 31;
    const int j    = blockIdx.x;
    const uint32_t sb = smem_u32(smem);

    // preload W slice (32 gate rows x 1024 fp16)
    {
        const __half* Whh = (const __half*)g_WhhH4;
        for (int idx = tx; idx < 32 * 128; idx += 256) {
            int row = idx >> 7, seg = idx & 127;
            int g = ((row >> 3) << 10) + (j << 3) + (row & 7);
            *(uint4*)(smem + SM_WHI + row * 2064 + seg * 16) =
                *(const uint4*)(Whh + (size_t)g * HH + seg * 8);
        }
    }

    float c[4] = {0.f, 0.f, 0.f, 0.f};

    const uint32_t aoff  = (uint32_t)((((wid << 4) + (lane & 15)) * 72 + ((lane >> 4) << 3)) * 2);
    const uint32_t wboff = (uint32_t)(((lane & 7) * 1032 + (((lane >> 3) & 1) << 3)) * 2);
    const uint32_t wb = sb + SM_WHI + wboff;

    const int srow = tx >> 3, sseg = tx & 7;
    const int r0  = (wid << 4) + (lane >> 2);
    const int nn0 = (lane & 3) << 1;

    const float* xpall = (const float*)g_xproj4;
    __syncthreads();

    for (int t = 0; t < TT; t++) {
        const __half* hcur = (const __half*)g_hbf4[t & 1];

        // prefetch x_proj for this step (independent of h / barrier)
        float2 xi[2], xf[2], xg[2], xo[2];
#pragma unroll
        for (int rh = 0; rh < 2; rh++) {
            const int row = r0 + (rh << 3);
            const float* bp = xpall + (size_t)t * BB * GG + (size_t)row * GG + (j << 3) + nn0;
            xi[rh] = *(const float2*)(bp);
            xf[rh] = *(const float2*)(bp + 1024);
            xg[rh] = *(const float2*)(bp + 2048);
            xo[rh] = *(const float2*)(bp + 3072);
        }

        float acc[4][4];
#pragma unroll
        for (int q = 0; q < 4; q++)
#pragma unroll
            for (int e = 0; e < 4; e++) acc[q][e] = 0.f;

        // prologue: stage k-tiles 0..2
#pragma unroll
        for (int s = 0; s < 3; s++) {
            const int k0 = s << 6;
#pragma unroll
            for (int r = 0; r < 4; r++) {
                int rr = srow + (r << 5);
                uint32_t d = rr * 144 + sseg * 16;
                CP16(sb + SM_A(s) + d, hcur + rr * HH + k0 + (sseg << 3));
            }
            CP_COMMIT();
        }

#pragma unroll 1
        for (int kt = 0; kt < 16; kt++) {
            if (kt <= 13)      CP_WAIT2();
            else if (kt == 14) CP_WAIT1();
            else               CP_WAIT0();
            __syncthreads();

            const uint32_t aA = sb + SM_A(kt & 3) + aoff;
#pragma unroll
            for (int ks = 0; ks < 4; ks++) {
                uint32_t ah[4];
                LDSM4(ah, aA + ks * 32);
                const uint32_t kcol = (uint32_t)(((kt << 6) + (ks << 4)) * 2);
#pragma unroll
                for (int q = 0; q < 4; q++) {
                    uint32_t bh[2];
                    LDSM2(bh, wb + q * 16512 + kcol);
                    MMA(acc[q], ah, bh);
                }
            }

            if (kt < 13) {
                const int k0 = (kt + 3) << 6;
                const int st = (kt + 3) & 3;
#pragma unroll
                for (int r = 0; r < 4; r++) {
                    int rr = srow + (r << 5);
                    uint32_t d = rr * 144 + sseg * 16;
                    CP16(sb + SM_A(st) + d, hcur + rr * HH + k0 + (sseg << 3));
                }
                CP_COMMIT();
            }
        }

        // epilogue (register-resident)
        __half* hnext = (__half*)g_hbf4[(t + 1) & 1];
#pragma unroll
        for (int rh = 0; rh < 2; rh++) {
            const int row = r0 + (rh << 3);
            float hv[2];
#pragma unroll
            for (int e = 0; e < 2; e++) {
                const int p = (rh << 1) + e;
                float gi = acc[0][p] + (e ? xi[rh].y : xi[rh].x);
                float gf = acc[1][p] + (e ? xf[rh].y : xf[rh].x);
                float gg = acc[2][p] + (e ? xg[rh].y : xg[rh].x);
                float go = acc[3][p] + (e ? xo[rh].y : xo[rh].x);
                float iv = 1.f / (1.f + __expf(-gi));
                float fv = 1.f / (1.f + __expf(-gf));
                float gv = tanhf(gg);
                float ov = 1.f / (1.f + __expf(-go));
                float cv = fv * c[p] + iv * gv;
                c[p] = cv;
                hv[e] = ov * tanhf(cv);
            }
            __half a0 = __float2half_rn(hv[0]);
            __half a1 = __float2half_rn(hv[1]);
            uint32_t ph = (uint32_t)__half_as_ushort(a0) | ((uint32_t)__half_as_ushort(a1) << 16);
            *(uint32_t*)(hnext + row * HH + (j << 3) + nn0) = ph;

            if (t == TT - 1) {
                float2 ov2; ov2.x = hv[0]; ov2.y = hv[1];
                *(float2*)(out + row * HH + (j << 3) + nn0) = ov2;
            }
        }

        grid_barrier(j, tx, (unsigned)(t + 1));
    }
}

// ---------------------------------------------------------------------------
extern "C" void kernel_launch(void* const* d_in, const int* in_sizes, int n_in,
                              void* d_out, int out_size)
{
    const float* x   = (const float*)d_in[0];
    const float* Wih = (const float*)d_in[1];
    const float* Whh = (const float*)d_in[2];
    const float* bih = (const float*)d_in[3];
    const float* bhh = (const float*)d_in[4];
    float* out = (float*)d_out;

    cudaFuncSetAttribute(lstm_mma_kernel, cudaFuncAttributeMaxDynamicSharedMemorySize, SM_TOT);
    cudaFuncSetAttribute(xproj_mma,       cudaFuncAttributeMaxDynamicSharedMemorySize, SMX_TOT);

    prep_whh<<<(int)(((size_t)GG * HH + 255) / 256), 256>>>(Whh);
    prep_wih<<<(int)(((size_t)GG * II + 255) / 256), 256>>>(Wih, bih, bhh);
    {
        dim3 g(TT / 32, II / 32, BB);
        dim3 bdim(32, 8);
        prep_x<<<g, bdim>>>(x);
    }
    {
        dim3 g(32, 2, BB);
        xproj_mma<<<g, 256, SMX_TOT>>>();
    }
    lstm_mma_kernel<<<128, 256, SM_TOT>>>(out);
}

// round 8
// speedup vs baseline: 1.4862x; 1.4862x over previous
#include <cuda_runtime.h>
#include <cuda_fp16.h>
#include <cstdint>
#include <math.h>

#define BB 128
#define II 512
#define TT 256
#define HH 1024
#define GG (4*HH)

// ---------------- scratch -----------------------------------------------
__device__ float4 g_xproj4[(size_t)TT * BB * GG / 4];       // [t][b][g] fp32
__device__ uint4  g_WhhH4[(size_t)GG * HH / 8];             // fp16 W_hh
__device__ uint4  g_WihH4[(size_t)GG * II / 8];             // fp16 W_ih
__device__ uint4  g_xT4[(size_t)BB * TT * II / 8];          // fp16 x^T [b][t][k]
__device__ uint4  g_hbf4[2][(size_t)BB * HH / 8];           // h fp16, double buffer
__device__ float  g_bias[GG];
__device__ unsigned g_cnt1[8][32];                          // leaf counters (128B apart)
__device__ unsigned g_cnt2;
__device__ unsigned g_gen;

// ---------------- helpers -----------------------------------------------
__device__ __forceinline__ uint32_t smem_u32(const void* p) {
    uint32_t a;
    asm("{ .reg .u64 t; cvta.to.shared.u64 t, %1; cvt.u32.u64 %0, t; }" : "=r"(a) : "l"(p));
    return a;
}
#define CP16(sa, ga) \
    asm volatile("cp.async.cg.shared.global [%0], [%1], 16;" :: "r"(sa), "l"(ga) : "memory")
#define CP_COMMIT() asm volatile("cp.async.commit_group;" ::: "memory")
#define CP_WAIT2()  asm volatile("cp.async.wait_group 2;" ::: "memory")
#define CP_WAIT1()  asm volatile("cp.async.wait_group 1;" ::: "memory")
#define CP_WAIT0()  asm volatile("cp.async.wait_group 0;" ::: "memory")

#define LDSM4(r, a) \
    asm volatile("ldmatrix.sync.aligned.m8n8.x4.shared.b16 {%0,%1,%2,%3}, [%4];" \
        : "=r"((r)[0]), "=r"((r)[1]), "=r"((r)[2]), "=r"((r)[3]) : "r"(a))
#define LDSM2(r, a) \
    asm volatile("ldmatrix.sync.aligned.m8n8.x2.shared.b16 {%0,%1}, [%2];" \
        : "=r"((r)[0]), "=r"((r)[1]) : "r"(a))
#define MMA(d, a, b) \
    asm volatile("mma.sync.aligned.m16n8k16.row.col.f32.f16.f16.f32 " \
        "{%0,%1,%2,%3}, {%4,%5,%6,%7}, {%8,%9}, {%0,%1,%2,%3};" \
        : "+f"((d)[0]), "+f"((d)[1]), "+f"((d)[2]), "+f"((d)[3]) \
        : "r"((a)[0]), "r"((a)[1]), "r"((a)[2]), "r"((a)[3]), "r"((b)[0]), "r"((b)[1]))

extern __shared__ char smem[];

// ---------------------------------------------------------------------------
// Prep kernels
// ---------------------------------------------------------------------------
__global__ void prep_whh(const float* __restrict__ Whh)
{
    size_t i = (size_t)blockIdx.x * blockDim.x + threadIdx.x;
    if (i < (size_t)GG * HH)
        ((__half*)g_WhhH4)[i] = __float2half_rn(Whh[i]);
    if (i < (size_t)BB * HH)
        ((__half*)g_hbf4[0])[i] = __float2half(0.f);
    if (i < 8 * 32)
        g_cnt1[i >> 5][i & 31] = 0;
    if (i == 0) { g_cnt2 = 0; g_gen = 0; }
}
__global__ void prep_wih(const float* __restrict__ Wih,
                         const float* __restrict__ bih,
                         const float* __restrict__ bhh)
{
    size_t i = (size_t)blockIdx.x * blockDim.x + threadIdx.x;
    if (i < (size_t)GG * II)
        ((__half*)g_WihH4)[i] = __float2half_rn(Wih[i]);
    if (i < GG)
        g_bias[i] = bih[i] + bhh[i];
}
// transpose: x[b][k][t] -> xT[b][t][k] fp16
__global__ void prep_x(const float* __restrict__ x)
{
    __shared__ float s[32][33];
    const int b = blockIdx.z, k0 = blockIdx.y * 32, t0 = blockIdx.x * 32;
    const int tx = threadIdx.x, ty = threadIdx.y;   // 32 x 8
    const float* xb = x + (size_t)b * II * TT;
#pragma unroll
    for (int i = 0; i < 4; i++)
        s[ty + 8 * i][tx] = xb[(size_t)(k0 + ty + 8 * i) * TT + t0 + tx];
    __syncthreads();
    __half* xh = (__half*)g_xT4;
    const size_t base = (size_t)b * TT * II;
#pragma unroll
    for (int i = 0; i < 4; i++) {
        float v = s[tx][ty + 8 * i];
        xh[base + (size_t)(t0 + ty + 8 * i) * II + k0 + tx] = __float2half_rn(v);
    }
}

// ---------------------------------------------------------------------------
// Phase 1: xproj via HMMA fp16 single-pass (unchanged from R6).
// ---------------------------------------------------------------------------
#define SMX_A(bf) ((bf)*36864)
#define SMX_B(bf) ((bf)*36864 + 18432)
#define SMX_TOT 73728

__global__ __launch_bounds__(256, 2) void xproj_mma(void)
{
    const int tx = threadIdx.x, wid = tx >> 5, lane = tx & 31;
    const int gt = blockIdx.x;
    const int tt = blockIdx.y;
    const int b  = blockIdx.z;
    const uint32_t sb = smem_u32(smem);
    const int wm = wid & 1, wn = wid >> 1;

    const __half* xh = (const __half*)g_xT4 + (size_t)b * TT * II + (size_t)tt * 128 * II;
    const __half* Wh = (const __half*)g_WihH4 + (size_t)gt * 128 * II;

    float acc[4][4][4];
#pragma unroll
    for (int f = 0; f < 4; f++)
#pragma unroll
        for (int q = 0; q < 4; q++)
#pragma unroll
            for (int e = 0; e < 4; e++) acc[f][q][e] = 0.f;

    const int srow = tx >> 3, sseg = tx & 7;

#pragma unroll
    for (int r = 0; r < 4; r++) {
        int row = srow + (r << 5);
        uint32_t d = row * 144 + sseg * 16;
        CP16(sb + SMX_A(0) + d, xh + (size_t)row * II + (sseg << 3));
        CP16(sb + SMX_B(0) + d, Wh + (size_t)row * II + (sseg << 3));
    }
    CP_COMMIT();

    int buf = 0;
    for (int kc = 0; kc < 8; kc++) {
        if (kc < 7) {
            const int k0 = (kc + 1) << 6;
#pragma unroll
            for (int r = 0; r < 4; r++) {
                int row = srow + (r << 5);
                uint32_t d = row * 144 + sseg * 16;
                CP16(sb + SMX_A(buf ^ 1) + d, xh + (size_t)row * II + k0 + (sseg << 3));
                CP16(sb + SMX_B(buf ^ 1) + d, Wh + (size_t)row * II + k0 + (sseg << 3));
            }
            CP_COMMIT();
            CP_WAIT1();
        } else {
            CP_WAIT0();
        }
        __syncthreads();

        const uint32_t aoff = (uint32_t)(((lane & 15) * 72 + ((lane >> 4) << 3)) * 2) + wm * 9216;
        const uint32_t aA = sb + SMX_A(buf) + aoff;
        const uint32_t bB = sb + SMX_B(buf) + wn * 4608
                          + (uint32_t)(((lane & 7) * 72 + (((lane >> 3) & 1) << 3)) * 2);
#pragma unroll
        for (int ks = 0; ks < 4; ks++) {
            uint32_t bh[4][2];
#pragma unroll
            for (int q = 0; q < 4; q++)
                LDSM2(bh[q], bB + q * 1152 + ks * 32);
#pragma unroll
            for (int f = 0; f < 4; f++) {
                uint32_t ah[4];
                LDSM4(ah, aA + f * 2304 + ks * 32);
#pragma unroll
                for (int q = 0; q < 4; q++)
                    MMA(acc[f][q], ah, bh[q]);
            }
        }
        __syncthreads();
        buf ^= 1;
    }

    float* xp = (float*)g_xproj4;
#pragma unroll
    for (int f = 0; f < 4; f++) {
        const int trow = tt * 128 + wm * 64 + f * 16 + (lane >> 2);
#pragma unroll
        for (int q = 0; q < 4; q++) {
            const int g = gt * 128 + wn * 32 + q * 8 + ((lane & 3) << 1);
            float2 bb = *(const float2*)&g_bias[g];
            float2 v0; v0.x = acc[f][q][0] + bb.x; v0.y = acc[f][q][1] + bb.y;
            float2 v1; v1.x = acc[f][q][2] + bb.x; v1.y = acc[f][q][3] + bb.y;
            *(float2*)&xp[((size_t)trow * BB + b) * GG + g]       = v0;
            *(float2*)&xp[((size_t)(trow + 8) * BB + b) * GG + g] = v1;
        }
    }
}

// ---------------------------------------------------------------------------
// Two-level monotonic grid barrier. Leaf: 8 counters x 16 CTAs; root: 8.
// All waiters poll the single g_gen line (L2 broadcast).
// ---------------------------------------------------------------------------
__device__ __forceinline__ void grid_sync_t(int j, int t)
{
    __syncthreads();
    if (threadIdx.x == 0) {
        __threadfence();
        const int grp = j >> 4;
        unsigned old = atomicAdd(&g_cnt1[grp][0], 1u);
        if (old == (unsigned)(t * 16 + 15)) {
            unsigned old2 = atomicAdd(&g_cnt2, 1u);
            if (old2 == (unsigned)(t * 8 + 7)) {
                __threadfence();
                *(volatile unsigned*)&g_gen = (unsigned)(t + 1);
            }
        }
        while (*(volatile unsigned*)&g_gen <= (unsigned)t) { }
        __threadfence();
    }
    __syncthreads();
}

// ---------------------------------------------------------------------------
// Phase 2: persistent HMMA recurrent kernel, fp16 single-pass.
// CTA j owns h cols [8j,8j+8) => 32 gate cols g = q*1024 + 8j + nn.
// Warp-private A staging: warp w loads only batch rows [16w,16w+16), 3-stage
// per-warp cp.async pipeline, NO __syncthreads in the k-loop.
// ---------------------------------------------------------------------------
#define SM_W 0
#define SM_AW(w, s) (66048 + ((w)*3 + (s))*2304)
#define SM_TOT (66048 + 8*3*2304)          // 121344

__global__ __launch_bounds__(256, 1) void lstm_mma_kernel(float* __restrict__ out)
{
    const int tx   = threadIdx.x;
    const int wid  = tx >> 5;
    const int lane = tx & 31;
    const int j    = blockIdx.x;
    const uint32_t sb = smem_u32(smem);

    // preload W slice (32 gate rows x 1024 fp16, row stride 2064B)
    {
        const __half* Whh = (const __half*)g_WhhH4;
        for (int idx = tx; idx < 32 * 128; idx += 256) {
            int row = idx >> 7, seg = idx & 127;
            int g = ((row >> 3) << 10) + (j << 3) + (row & 7);
            *(uint4*)(smem + SM_W + row * 2064 + seg * 16) =
                *(const uint4*)(Whh + (size_t)g * HH + seg * 8);
        }
    }

    float c[4] = {0.f, 0.f, 0.f, 0.f};

    const int wrb = wid << 4;                      // warp's batch-row base
    const uint32_t aoff = (uint32_t)((lane & 15) * 144 + ((lane >> 4) << 4));
    const uint32_t wboff = (uint32_t)(((lane & 7) * 1032 + (((lane >> 3) & 1) << 3)) * 2);
    const uint32_t wb = sb + SM_W + wboff;

    const int r0  = (wid << 4) + (lane >> 2);
    const int nn0 = (lane & 3) << 1;

    const float* xpall = (const float*)g_xproj4;
    __syncthreads();                               // W resident

    for (int t = 0; t < TT; t++) {
        const __half* hcur = (const __half*)g_hbf4[t & 1];

        // x_proj prefetch (DRAM latency hidden under the MMA loop)
        float2 xi[2], xf[2], xg[2], xo[2];
#pragma unroll
        for (int rh = 0; rh < 2; rh++) {
            const int row = r0 + (rh << 3);
            const float* bp = xpall + (size_t)t * BB * GG + (size_t)row * GG + (j << 3) + nn0;
            xi[rh] = *(const float2*)(bp);
            xf[rh] = *(const float2*)(bp + 1024);
            xg[rh] = *(const float2*)(bp + 2048);
            xo[rh] = *(const float2*)(bp + 3072);
        }

        float acc[4][4];
#pragma unroll
        for (int q = 0; q < 4; q++)
#pragma unroll
            for (int e = 0; e < 4; e++) acc[q][e] = 0.f;

        // prologue: warp-private stages 0..2 (k-tiles 0..2)
#pragma unroll
        for (int s = 0; s < 3; s++) {
            const int k0 = s << 6;
#pragma unroll
            for (int r = 0; r < 4; r++) {
                int ch = lane + (r << 5);          // 0..127
                int row = ch >> 3, seg = ch & 7;
                CP16(sb + SM_AW(wid, s) + row * 144 + seg * 16,
                     hcur + (size_t)(wrb + row) * HH + k0 + (seg << 3));
            }
            CP_COMMIT();
        }

#pragma unroll 1
        for (int kt = 0; kt < 16; kt++) {
            if (kt <= 13)      CP_WAIT2();
            else if (kt == 14) CP_WAIT1();
            else               CP_WAIT0();

            const uint32_t aA = sb + SM_AW(wid, kt % 3) + aoff;
#pragma unroll
            for (int ks = 0; ks < 4; ks++) {
                uint32_t ah[4];
                LDSM4(ah, aA + ks * 32);
                const uint32_t kcol = (uint32_t)(((kt << 6) + (ks << 4)) * 2);
#pragma unroll
                for (int q = 0; q < 4; q++) {
                    uint32_t bh[2];
                    LDSM2(bh, wb + q * 16512 + kcol);
                    MMA(acc[q], ah, bh);
                }
            }

            if (kt < 13) {
                const int k0 = (kt + 3) << 6;
                const int st = (kt + 3) % 3;
#pragma unroll
                for (int r = 0; r < 4; r++) {
                    int ch = lane + (r << 5);
                    int row = ch >> 3, seg = ch & 7;
                    CP16(sb + SM_AW(wid, st) + row * 144 + seg * 16,
                         hcur + (size_t)(wrb + row) * HH + k0 + (seg << 3));
                }
                CP_COMMIT();
            }
        }

        // epilogue (register-resident cell update)
        __half* hnext = (__half*)g_hbf4[(t + 1) & 1];
#pragma unroll
        for (int rh = 0; rh < 2; rh++) {
            const int row = r0 + (rh << 3);
            float hv[2];
#pragma unroll
            for (int e = 0; e < 2; e++) {
                const int p = (rh << 1) + e;
                float gi = acc[0][p] + (e ? xi[rh].y : xi[rh].x);
                float gf = acc[1][p] + (e ? xf[rh].y : xf[rh].x);
                float gg = acc[2][p] + (e ? xg[rh].y : xg[rh].x);
                float go = acc[3][p] + (e ? xo[rh].y : xo[rh].x);
                float iv = 1.f / (1.f + __expf(-gi));
                float fv = 1.f / (1.f + __expf(-gf));
                float gv = tanhf(gg);
                float ov = 1.f / (1.f + __expf(-go));
                float cv = fv * c[p] + iv * gv;
                c[p] = cv;
                hv[e] = ov * tanhf(cv);
            }
            __half a0 = __float2half_rn(hv[0]);
            __half a1 = __float2half_rn(hv[1]);
            uint32_t ph = (uint32_t)__half_as_ushort(a0) | ((uint32_t)__half_as_ushort(a1) << 16);
            *(uint32_t*)(hnext + row * HH + (j << 3) + nn0) = ph;

            if (t == TT - 1) {
                float2 ov2; ov2.x = hv[0]; ov2.y = hv[1];
                *(float2*)(out + row * HH + (j << 3) + nn0) = ov2;
            }
        }

        if (t < TT - 1)
            grid_sync_t(j, t);
    }
}

// ---------------------------------------------------------------------------
extern "C" void kernel_launch(void* const* d_in, const int* in_sizes, int n_in,
                              void* d_out, int out_size)
{
    const float* x   = (const float*)d_in[0];
    const float* Wih = (const float*)d_in[1];
    const float* Whh = (const float*)d_in[2];
    const float* bih = (const float*)d_in[3];
    const float* bhh = (const float*)d_in[4];
    float* out = (float*)d_out;

    cudaFuncSetAttribute(lstm_mma_kernel, cudaFuncAttributeMaxDynamicSharedMemorySize, SM_TOT);
    cudaFuncSetAttribute(xproj_mma,       cudaFuncAttributeMaxDynamicSharedMemorySize, SMX_TOT);

    prep_whh<<<(int)(((size_t)GG * HH + 255) / 256), 256>>>(Whh);
    prep_wih<<<(int)(((size_t)GG * II + 255) / 256), 256>>>(Wih, bih, bhh);
    {
        dim3 g(TT / 32, II / 32, BB);
        dim3 bdim(32, 8);
        prep_x<<<g, bdim>>>(x);
    }
    {
        dim3 g(32, 2, BB);
        xproj_mma<<<g, 256, SMX_TOT>>>();
    }
    lstm_mma_kernel<<<128, 256, SM_TOT>>>(out);
}

// round 9
// speedup vs baseline: 1.5706x; 1.0568x over previous
#include <cuda_runtime.h>
#include <cuda_fp16.h>
#include <cstdint>
#include <math.h>

#define BB 128
#define II 512
#define TT 256
#define HH 1024
#define GG (4*HH)

// ---------------- scratch -----------------------------------------------
__device__ float4 g_xproj4[(size_t)TT * BB * GG / 4];       // [t][b][g] fp32
__device__ uint4  g_WhhH4[(size_t)GG * HH / 8];             // fp16 W_hh
__device__ uint4  g_WihH4[(size_t)GG * II / 8];             // fp16 W_ih
__device__ uint4  g_xT4[(size_t)BB * TT * II / 8];          // fp16 x^T [b][t][k]
__device__ uint4  g_hbf4[2][(size_t)BB * HH / 8];           // h fp16, double buffer
__device__ float  g_bias[GG];
__device__ unsigned g_cnt1[8][32];                          // leaf counters (128B apart)
__device__ unsigned g_cnt2;
__device__ unsigned g_gen;

// ---------------- helpers -----------------------------------------------
__device__ __forceinline__ uint32_t smem_u32(const void* p) {
    uint32_t a;
    asm("{ .reg .u64 t; cvta.to.shared.u64 t, %1; cvt.u32.u64 %0, t; }" : "=r"(a) : "l"(p));
    return a;
}
#define CP16(sa, ga) \
    asm volatile("cp.async.cg.shared.global [%0], [%1], 16;" :: "r"(sa), "l"(ga) : "memory")
#define CP_COMMIT() asm volatile("cp.async.commit_group;" ::: "memory")
#define CP_WAITN(n) asm volatile("cp.async.wait_group %0;" :: "n"(n) : "memory")

#define LDSM4(r, a) \
    asm volatile("ldmatrix.sync.aligned.m8n8.x4.shared.b16 {%0,%1,%2,%3}, [%4];" \
        : "=r"((r)[0]), "=r"((r)[1]), "=r"((r)[2]), "=r"((r)[3]) : "r"(a))
#define LDSM2(r, a) \
    asm volatile("ldmatrix.sync.aligned.m8n8.x2.shared.b16 {%0,%1}, [%2];" \
        : "=r"((r)[0]), "=r"((r)[1]) : "r"(a))
#define MMA(d, a0, a1, a2, a3, b0, b1) \
    asm volatile("mma.sync.aligned.m16n8k16.row.col.f32.f16.f16.f32 " \
        "{%0,%1,%2,%3}, {%4,%5,%6,%7}, {%8,%9}, {%0,%1,%2,%3};" \
        : "+f"((d)[0]), "+f"((d)[1]), "+f"((d)[2]), "+f"((d)[3]) \
        : "r"(a0), "r"(a1), "r"(a2), "r"(a3), "r"(b0), "r"(b1))
#define MMA4(d, a, b) MMA(d, (a)[0], (a)[1], (a)[2], (a)[3], (b)[0], (b)[1])

extern __shared__ char smem[];

// ---------------------------------------------------------------------------
// Prep kernels
// ---------------------------------------------------------------------------
__global__ void prep_whh(const float* __restrict__ Whh)
{
    size_t i = (size_t)blockIdx.x * blockDim.x + threadIdx.x;
    if (i < (size_t)GG * HH)
        ((__half*)g_WhhH4)[i] = __float2half_rn(Whh[i]);
    if (i < (size_t)BB * HH)
        ((__half*)g_hbf4[0])[i] = __float2half(0.f);
    if (i < 8 * 32)
        g_cnt1[i >> 5][i & 31] = 0;
    if (i == 0) { g_cnt2 = 0; g_gen = 0; }
}
__global__ void prep_wih(const float* __restrict__ Wih,
                         const float* __restrict__ bih,
                         const float* __restrict__ bhh)
{
    size_t i = (size_t)blockIdx.x * blockDim.x + threadIdx.x;
    if (i < (size_t)GG * II)
        ((__half*)g_WihH4)[i] = __float2half_rn(Wih[i]);
    if (i < GG)
        g_bias[i] = bih[i] + bhh[i];
}
// transpose: x[b][k][t] -> xT[b][t][k] fp16
__global__ void prep_x(const float* __restrict__ x)
{
    __shared__ float s[32][33];
    const int b = blockIdx.z, k0 = blockIdx.y * 32, t0 = blockIdx.x * 32;
    const int tx = threadIdx.x, ty = threadIdx.y;   // 32 x 8
    const float* xb = x + (size_t)b * II * TT;
#pragma unroll
    for (int i = 0; i < 4; i++)
        s[ty + 8 * i][tx] = xb[(size_t)(k0 + ty + 8 * i) * TT + t0 + tx];
    __syncthreads();
    __half* xh = (__half*)g_xT4;
    const size_t base = (size_t)b * TT * II;
#pragma unroll
    for (int i = 0; i < 4; i++) {
        float v = s[tx][ty + 8 * i];
        xh[base + (size_t)(t0 + ty + 8 * i) * II + k0 + tx] = __float2half_rn(v);
    }
}

// ---------------------------------------------------------------------------
// Phase 1: xproj via HMMA fp16 single-pass (unchanged).
// ---------------------------------------------------------------------------
#define SMX_A(bf) ((bf)*36864)
#define SMX_B(bf) ((bf)*36864 + 18432)
#define SMX_TOT 73728

__global__ __launch_bounds__(256, 2) void xproj_mma(void)
{
    const int tx = threadIdx.x, wid = tx >> 5, lane = tx & 31;
    const int gt = blockIdx.x;
    const int tt = blockIdx.y;
    const int b  = blockIdx.z;
    const uint32_t sb = smem_u32(smem);
    const int wm = wid & 1, wn = wid >> 1;

    const __half* xh = (const __half*)g_xT4 + (size_t)b * TT * II + (size_t)tt * 128 * II;
    const __half* Wh = (const __half*)g_WihH4 + (size_t)gt * 128 * II;

    float acc[4][4][4];
#pragma unroll
    for (int f = 0; f < 4; f++)
#pragma unroll
        for (int q = 0; q < 4; q++)
#pragma unroll
            for (int e = 0; e < 4; e++) acc[f][q][e] = 0.f;

    const int srow = tx >> 3, sseg = tx & 7;

#pragma unroll
    for (int r = 0; r < 4; r++) {
        int row = srow + (r << 5);
        uint32_t d = row * 144 + sseg * 16;
        CP16(sb + SMX_A(0) + d, xh + (size_t)row * II + (sseg << 3));
        CP16(sb + SMX_B(0) + d, Wh + (size_t)row * II + (sseg << 3));
    }
    CP_COMMIT();

    int buf = 0;
    for (int kc = 0; kc < 8; kc++) {
        if (kc < 7) {
            const int k0 = (kc + 1) << 6;
#pragma unroll
            for (int r = 0; r < 4; r++) {
                int row = srow + (r << 5);
                uint32_t d = row * 144 + sseg * 16;
                CP16(sb + SMX_A(buf ^ 1) + d, xh + (size_t)row * II + k0 + (sseg << 3));
                CP16(sb + SMX_B(buf ^ 1) + d, Wh + (size_t)row * II + k0 + (sseg << 3));
            }
            CP_COMMIT();
            CP_WAITN(1);
        } else {
            CP_WAITN(0);
        }
        __syncthreads();

        const uint32_t aoff = (uint32_t)(((lane & 15) * 72 + ((lane >> 4) << 3)) * 2) + wm * 9216;
        const uint32_t aA = sb + SMX_A(buf) + aoff;
        const uint32_t bB = sb + SMX_B(buf) + wn * 4608
                          + (uint32_t)(((lane & 7) * 72 + (((lane >> 3) & 1) << 3)) * 2);
#pragma unroll
        for (int ks = 0; ks < 4; ks++) {
            uint32_t bh[4][2];
#pragma unroll
            for (int q = 0; q < 4; q++)
                LDSM2(bh[q], bB + q * 1152 + ks * 32);
#pragma unroll
            for (int f = 0; f < 4; f++) {
                uint32_t ah[4];
                LDSM4(ah, aA + f * 2304 + ks * 32);
#pragma unroll
                for (int q = 0; q < 4; q++)
                    MMA4(acc[f][q], ah, bh[q]);
            }
        }
        __syncthreads();
        buf ^= 1;
    }

    float* xp = (float*)g_xproj4;
#pragma unroll
    for (int f = 0; f < 4; f++) {
        const int trow = tt * 128 + wm * 64 + f * 16 + (lane >> 2);
#pragma unroll
        for (int q = 0; q < 4; q++) {
            const int g = gt * 128 + wn * 32 + q * 8 + ((lane & 3) << 1);
            float2 bb = *(const float2*)&g_bias[g];
            float2 v0; v0.x = acc[f][q][0] + bb.x; v0.y = acc[f][q][1] + bb.y;
            float2 v1; v1.x = acc[f][q][2] + bb.x; v1.y = acc[f][q][3] + bb.y;
            *(float2*)&xp[((size_t)trow * BB + b) * GG + g]       = v0;
            *(float2*)&xp[((size_t)(trow + 8) * BB + b) * GG + g] = v1;
        }
    }
}

// ---------------------------------------------------------------------------
// Two-level monotonic grid barrier (proven in R8).
// ---------------------------------------------------------------------------
__device__ __forceinline__ void grid_sync_t(int j, int t)
{
    __syncthreads();
    if (threadIdx.x == 0) {
        __threadfence();
        const int grp = j >> 4;
        unsigned old = atomicAdd(&g_cnt1[grp][0], 1u);
        if (old == (unsigned)(t * 16 + 15)) {
            unsigned old2 = atomicAdd(&g_cnt2, 1u);
            if (old2 == (unsigned)(t * 8 + 7)) {
                __threadfence();
                *(volatile unsigned*)&g_gen = (unsigned)(t + 1);
            }
        }
        while (*(volatile unsigned*)&g_gen <= (unsigned)t) { }
        __threadfence();
    }
    __syncthreads();
}

// ---------------------------------------------------------------------------
// Phase 2: persistent HMMA recurrent kernel.
// CTA j owns h cols [8j,8j+8) => 32 gate cols g = q*1024 + 8j + nn.
// Warp-private A staging, 5-stage cp.async pipeline, loads issued before
// compute, B-operand via LDSM4 (two k-steps per load).
// ---------------------------------------------------------------------------
#define SM_W 0
#define SM_AW(w, s) (66048 + ((w)*5 + (s))*2304)
#define SM_TOT (66048 + 8*5*2304)          // 158208

__global__ __launch_bounds__(256, 1) void lstm_mma_kernel(float* __restrict__ out)
{
    const int tx   = threadIdx.x;
    const int wid  = tx >> 5;
    const int lane = tx & 31;
    const int j    = blockIdx.x;
    const uint32_t sb = smem_u32(smem);

    // preload W slice (32 gate rows x 1024 fp16, row stride 2064B)
    {
        const __half* Whh = (const __half*)g_WhhH4;
        for (int idx = tx; idx < 32 * 128; idx += 256) {
            int row = idx >> 7, seg = idx & 127;
            int g = ((row >> 3) << 10) + (j << 3) + (row & 7);
            *(uint4*)(smem + SM_W + row * 2064 + seg * 16) =
                *(const uint4*)(Whh + (size_t)g * HH + seg * 8);
        }
    }

    float c[4] = {0.f, 0.f, 0.f, 0.f};

    const int wrb = wid << 4;                      // warp's batch-row base
    const uint32_t aoff = (uint32_t)((lane & 15) * 144 + ((lane >> 4) << 4));
    // B via x4: lanes {0-7,8-15,16-23,24-31} -> gate row (lane&7), k-offset
    // ((lane>>3)&3)*16B -> regs {b0,b1}=ks, {b2,b3}=ks+1
    const uint32_t wboff = (uint32_t)((lane & 7) * 2064 + (((lane >> 3) & 3) << 4));
    const uint32_t wb = sb + SM_W + wboff;

    const int r0  = (wid << 4) + (lane >> 2);
    const int nn0 = (lane & 3) << 1;

    const float* xpall = (const float*)g_xproj4;
    __syncthreads();                               // W resident

    for (int t = 0; t < TT; t++) {
        const __half* hcur = (const __half*)g_hbf4[t & 1];

        // x_proj prefetch (latency hidden under the MMA loop)
        float2 xi[2], xf[2], xg[2], xo[2];
#pragma unroll
        for (int rh = 0; rh < 2; rh++) {
            const int row = r0 + (rh << 3);
            const float* bp = xpall + (size_t)t * BB * GG + (size_t)row * GG + (j << 3) + nn0;
            xi[rh] = *(const float2*)(bp);
            xf[rh] = *(const float2*)(bp + 1024);
            xg[rh] = *(const float2*)(bp + 2048);
            xo[rh] = *(const float2*)(bp + 3072);
        }

        float acc[4][4];
#pragma unroll
        for (int q = 0; q < 4; q++)
#pragma unroll
            for (int e = 0; e < 4; e++) acc[q][e] = 0.f;

        // prologue: stage k-tiles 0..3 into warp-private buffers
#pragma unroll
        for (int s = 0; s < 4; s++) {
            const int k0 = s << 6;
#pragma unroll
            for (int r = 0; r < 4; r++) {
                int ch = lane + (r << 5);          // 0..127
                int row = ch >> 3, seg = ch & 7;
                CP16(sb + SM_AW(wid, s) + row * 144 + seg * 16,
                     hcur + (size_t)(wrb + row) * HH + k0 + (seg << 3));
            }
            CP_COMMIT();
        }

#pragma unroll 2
        for (int kt = 0; kt < 16; kt++) {
            // issue k-tile kt+4 first (earliest possible start), then wait for kt
            if (kt < 12) {
                const int k0 = (kt + 4) << 6;
                const int st = (kt + 4) % 5;
#pragma unroll
                for (int r = 0; r < 4; r++) {
                    int ch = lane + (r << 5);
                    int row = ch >> 3, seg = ch & 7;
                    CP16(sb + SM_AW(wid, st) + row * 144 + seg * 16,
                         hcur + (size_t)(wrb + row) * HH + k0 + (seg << 3));
                }
                CP_COMMIT();
                CP_WAITN(4);
            } else if (kt == 12) CP_WAITN(3);
            else if (kt == 13)   CP_WAITN(2);
            else if (kt == 14)   CP_WAITN(1);
            else                 CP_WAITN(0);

            const uint32_t aA = sb + SM_AW(wid, kt % 5) + aoff;
#pragma unroll
            for (int ks2 = 0; ks2 < 2; ks2++) {
                uint32_t ah0[4], ah1[4];
                LDSM4(ah0, aA + (ks2 << 6));
                LDSM4(ah1, aA + (ks2 << 6) + 32);
                const uint32_t kcol = (uint32_t)((kt << 7) + (ks2 << 6));
#pragma unroll
                for (int q = 0; q < 4; q++) {
                    uint32_t bh[4];
                    LDSM4(bh, wb + q * 16512 + kcol);
                    MMA(acc[q], ah0[0], ah0[1], ah0[2], ah0[3], bh[0], bh[1]);
                    MMA(acc[q], ah1[0], ah1[1], ah1[2], ah1[3], bh[2], bh[3]);
                }
            }
        }

        // epilogue (register-resident cell update)
        __half* hnext = (__half*)g_hbf4[(t + 1) & 1];
#pragma unroll
        for (int rh = 0; rh < 2; rh++) {
            const int row = r0 + (rh << 3);
            float hv[2];
#pragma unroll
            for (int e = 0; e < 2; e++) {
                const int p = (rh << 1) + e;
                float gi = acc[0][p] + (e ? xi[rh].y : xi[rh].x);
                float gf = acc[1][p] + (e ? xf[rh].y : xf[rh].x);
                float gg = acc[2][p] + (e ? xg[rh].y : xg[rh].x);
                float go = acc[3][p] + (e ? xo[rh].y : xo[rh].x);
                float iv = 1.f / (1.f + __expf(-gi));
                float fv = 1.f / (1.f + __expf(-gf));
                float gv = tanhf(gg);
                float ov = 1.f / (1.f + __expf(-go));
                float cv = fv * c[p] + iv * gv;
                c[p] = cv;
                hv[e] = ov * tanhf(cv);
            }
            __half a0 = __float2half_rn(hv[0]);
            __half a1 = __float2half_rn(hv[1]);
            uint32_t ph = (uint32_t)__half_as_ushort(a0) | ((uint32_t)__half_as_ushort(a1) << 16);
            *(uint32_t*)(hnext + row * HH + (j << 3) + nn0) = ph;

            if (t == TT - 1) {
                float2 ov2; ov2.x = hv[0]; ov2.y = hv[1];
                *(float2*)(out + row * HH + (j << 3) + nn0) = ov2;
            }
        }

        if (t < TT - 1)
            grid_sync_t(j, t);
    }
}

// ---------------------------------------------------------------------------
extern "C" void kernel_launch(void* const* d_in, const int* in_sizes, int n_in,
                              void* d_out, int out_size)
{
    const float* x   = (const float*)d_in[0];
    const float* Wih = (const float*)d_in[1];
    const float* Whh = (const float*)d_in[2];
    const float* bih = (const float*)d_in[3];
    const float* bhh = (const float*)d_in[4];
    float* out = (float*)d_out;

    cudaFuncSetAttribute(lstm_mma_kernel, cudaFuncAttributeMaxDynamicSharedMemorySize, SM_TOT);
    cudaFuncSetAttribute(xproj_mma,       cudaFuncAttributeMaxDynamicSharedMemorySize, SMX_TOT);

    prep_whh<<<(int)(((size_t)GG * HH + 255) / 256), 256>>>(Whh);
    prep_wih<<<(int)(((size_t)GG * II + 255) / 256), 256>>>(Wih, bih, bhh);
    {
        dim3 g(TT / 32, II / 32, BB);
        dim3 bdim(32, 8);
        prep_x<<<g, bdim>>>(x);
    }
    {
        dim3 g(32, 2, BB);
        xproj_mma<<<g, 256, SMX_TOT>>>();
    }
    lstm_mma_kernel<<<128, 256, SM_TOT>>>(out);
}

// round 10
// speedup vs baseline: 1.6083x; 1.0240x over previous
#include <cuda_runtime.h>
#include <cuda_fp16.h>
#include <cstdint>
#include <math.h>

#define BB 128
#define II 512
#define TT 256
#define HH 1024
#define GG (4*HH)

// ---------------- scratch -----------------------------------------------
__device__ float4 g_xproj4[(size_t)TT * BB * GG / 4];       // [t][b][g] fp32
__device__ uint4  g_WhhH4[(size_t)GG * HH / 8];             // fp16 W_hh
__device__ uint4  g_WihH4[(size_t)GG * II / 8];             // fp16 W_ih
__device__ uint4  g_xT4[(size_t)BB * TT * II / 8];          // fp16 x^T [b][t][k]
__device__ uint4  g_hbf4[2][(size_t)BB * HH / 8];           // h fp16, double buffer
__device__ float  g_bias[GG];
__device__ unsigned g_cnt1[2][4][32];                       // [bh][leaf grp] counters
__device__ unsigned g_cnt2[2][32];                          // [bh] root counter
__device__ unsigned g_genv[2][32];                          // [bh] generation

// ---------------- helpers -----------------------------------------------
__device__ __forceinline__ uint32_t smem_u32(const void* p) {
    uint32_t a;
    asm("{ .reg .u64 t; cvta.to.shared.u64 t, %1; cvt.u32.u64 %0, t; }" : "=r"(a) : "l"(p));
    return a;
}
#define CP16(sa, ga) \
    asm volatile("cp.async.cg.shared.global [%0], [%1], 16;" :: "r"(sa), "l"(ga) : "memory")
#define CP_COMMIT() asm volatile("cp.async.commit_group;" ::: "memory")
#define CP_WAITN(n) asm volatile("cp.async.wait_group %0;" :: "n"(n) : "memory")
#define BARW(id)    asm volatile("bar.sync %0, 64;" :: "r"(id) : "memory")

#define LDSM4(r, a) \
    asm volatile("ldmatrix.sync.aligned.m8n8.x4.shared.b16 {%0,%1,%2,%3}, [%4];" \
        : "=r"((r)[0]), "=r"((r)[1]), "=r"((r)[2]), "=r"((r)[3]) : "r"(a))
#define LDSM2(r, a) \
    asm volatile("ldmatrix.sync.aligned.m8n8.x2.shared.b16 {%0,%1}, [%2];" \
        : "=r"((r)[0]), "=r"((r)[1]) : "r"(a))
#define MMA(d, a0, a1, a2, a3, b0, b1) \
    asm volatile("mma.sync.aligned.m16n8k16.row.col.f32.f16.f16.f32 " \
        "{%0,%1,%2,%3}, {%4,%5,%6,%7}, {%8,%9}, {%0,%1,%2,%3};" \
        : "+f"((d)[0]), "+f"((d)[1]), "+f"((d)[2]), "+f"((d)[3]) \
        : "r"(a0), "r"(a1), "r"(a2), "r"(a3), "r"(b0), "r"(b1))
#define MMA4(d, a, b) MMA(d, (a)[0], (a)[1], (a)[2], (a)[3], (b)[0], (b)[1])

extern __shared__ char smem[];

// ---------------------------------------------------------------------------
// Prep kernels
// ---------------------------------------------------------------------------
__global__ void prep_whh(const float* __restrict__ Whh)
{
    size_t i = (size_t)blockIdx.x * blockDim.x + threadIdx.x;
    if (i < (size_t)GG * HH)
        ((__half*)g_WhhH4)[i] = __float2half_rn(Whh[i]);
    if (i < (size_t)BB * HH)
        ((__half*)g_hbf4[0])[i] = __float2half(0.f);
    if (i < 2 * 4 * 32)
        ((unsigned*)g_cnt1)[i] = 0;
    if (i < 2 * 32) { ((unsigned*)g_cnt2)[i] = 0; ((unsigned*)g_genv)[i] = 0; }
}
__global__ void prep_wih(const float* __restrict__ Wih,
                         const float* __restrict__ bih,
                         const float* __restrict__ bhh)
{
    size_t i = (size_t)blockIdx.x * blockDim.x + threadIdx.x;
    if (i < (size_t)GG * II)
        ((__half*)g_WihH4)[i] = __float2half_rn(Wih[i]);
    if (i < GG)
        g_bias[i] = bih[i] + bhh[i];
}
// transpose: x[b][k][t] -> xT[b][t][k] fp16
__global__ void prep_x(const float* __restrict__ x)
{
    __shared__ float s[32][33];
    const int b = blockIdx.z, k0 = blockIdx.y * 32, t0 = blockIdx.x * 32;
    const int tx = threadIdx.x, ty = threadIdx.y;   // 32 x 8
    const float* xb = x + (size_t)b * II * TT;
#pragma unroll
    for (int i = 0; i < 4; i++)
        s[ty + 8 * i][tx] = xb[(size_t)(k0 + ty + 8 * i) * TT + t0 + tx];
    __syncthreads();
    __half* xh = (__half*)g_xT4;
    const size_t base = (size_t)b * TT * II;
#pragma unroll
    for (int i = 0; i < 4; i++) {
        float v = s[tx][ty + 8 * i];
        xh[base + (size_t)(t0 + ty + 8 * i) * II + k0 + tx] = __float2half_rn(v);
    }
}

// ---------------------------------------------------------------------------
// Phase 1: xproj via HMMA fp16 single-pass (unchanged).
// ---------------------------------------------------------------------------
#define SMX_A(bf) ((bf)*36864)
#define SMX_B(bf) ((bf)*36864 + 18432)
#define SMX_TOT 73728

__global__ __launch_bounds__(256, 2) void xproj_mma(void)
{
    const int tx = threadIdx.x, wid = tx >> 5, lane = tx & 31;
    const int gt = blockIdx.x;
    const int tt = blockIdx.y;
    const int b  = blockIdx.z;
    const uint32_t sb = smem_u32(smem);
    const int wm = wid & 1, wn = wid >> 1;

    const __half* xh = (const __half*)g_xT4 + (size_t)b * TT * II + (size_t)tt * 128 * II;
    const __half* Wh = (const __half*)g_WihH4 + (size_t)gt * 128 * II;

    float acc[4][4][4];
#pragma unroll
    for (int f = 0; f < 4; f++)
#pragma unroll
        for (int q = 0; q < 4; q++)
#pragma unroll
            for (int e = 0; e < 4; e++) acc[f][q][e] = 0.f;

    const int srow = tx >> 3, sseg = tx & 7;

#pragma unroll
    for (int r = 0; r < 4; r++) {
        int row = srow + (r << 5);
        uint32_t d = row * 144 + sseg * 16;
        CP16(sb + SMX_A(0) + d, xh + (size_t)row * II + (sseg << 3));
        CP16(sb + SMX_B(0) + d, Wh + (size_t)row * II + (sseg << 3));
    }
    CP_COMMIT();

    int buf = 0;
    for (int kc = 0; kc < 8; kc++) {
        if (kc < 7) {
            const int k0 = (kc + 1) << 6;
#pragma unroll
            for (int r = 0; r < 4; r++) {
                int row = srow + (r << 5);
                uint32_t d = row * 144 + sseg * 16;
                CP16(sb + SMX_A(buf ^ 1) + d, xh + (size_t)row * II + k0 + (sseg << 3));
                CP16(sb + SMX_B(buf ^ 1) + d, Wh + (size_t)row * II + k0 + (sseg << 3));
            }
            CP_COMMIT();
            CP_WAITN(1);
        } else {
            CP_WAITN(0);
        }
        __syncthreads();

        const uint32_t aoff = (uint32_t)(((lane & 15) * 72 + ((lane >> 4) << 3)) * 2) + wm * 9216;
        const uint32_t aA = sb + SMX_A(buf) + aoff;
        const uint32_t bB = sb + SMX_B(buf) + wn * 4608
                          + (uint32_t)(((lane & 7) * 72 + (((lane >> 3) & 1) << 3)) * 2);
#pragma unroll
        for (int ks = 0; ks < 4; ks++) {
            uint32_t bh[4][2];
#pragma unroll
            for (int q = 0; q < 4; q++)
                LDSM2(bh[q], bB + q * 1152 + ks * 32);
#pragma unroll
            for (int f = 0; f < 4; f++) {
                uint32_t ah[4];
                LDSM4(ah, aA + f * 2304 + ks * 32);
#pragma unroll
                for (int q = 0; q < 4; q++)
                    MMA4(acc[f][q], ah, bh[q]);
            }
        }
        __syncthreads();
        buf ^= 1;
    }

    float* xp = (float*)g_xproj4;
#pragma unroll
    for (int f = 0; f < 4; f++) {
        const int trow = tt * 128 + wm * 64 + f * 16 + (lane >> 2);
#pragma unroll
        for (int q = 0; q < 4; q++) {
            const int g = gt * 128 + wn * 32 + q * 8 + ((lane & 3) << 1);
            float2 bb = *(const float2*)&g_bias[g];
            float2 v0; v0.x = acc[f][q][0] + bb.x; v0.y = acc[f][q][1] + bb.y;
            float2 v1; v1.x = acc[f][q][2] + bb.x; v1.y = acc[f][q][3] + bb.y;
            *(float2*)&xp[((size_t)trow * BB + b) * GG + g]       = v0;
            *(float2*)&xp[((size_t)(trow + 8) * BB + b) * GG + g] = v1;
        }
    }
}

// ---------------------------------------------------------------------------
// Per-half two-level grid barrier: 64 CTAs/half, leaf 4x16, root 4.
// ---------------------------------------------------------------------------
__device__ __forceinline__ void grid_sync_t(int bh, int jj, int t)
{
    __syncthreads();
    if (threadIdx.x == 0) {
        __threadfence();
        const int grp = jj >> 4;
        unsigned old = atomicAdd(&g_cnt1[bh][grp][0], 1u);
        if (old == (unsigned)(t * 16 + 15)) {
            unsigned old2 = atomicAdd(&g_cnt2[bh][0], 1u);
            if (old2 == (unsigned)(t * 4 + 3)) {
                __threadfence();
                *(volatile unsigned*)&g_genv[bh][0] = (unsigned)(t + 1);
            }
        }
        while (*(volatile unsigned*)&g_genv[bh][0] <= (unsigned)t) { }
        __threadfence();
    }
    __syncthreads();
}

// ---------------------------------------------------------------------------
// Phase 2: persistent HMMA recurrent kernel, M/N-split decomposition.
// CTA (jj, bh): jj owns h cols [16jj,16jj+16) (=> 64 gate cols), bh = batch
// half (rows 64bh..64bh+63). Warp (wm=wid&3, wn=wid>>2) computes rows
// [16wm,16wm+16) x gate cols q*1024 + 16jj + 8wn + [0,8).
// A staging shared per wm-pair (warps wm, wm+4) with named-barrier sync; each
// warp cp.asyncs its 8 rows. 5-stage pipeline, no __syncthreads in k-loop.
// ---------------------------------------------------------------------------
#define SM_W 0
#define SM_AW(wm, s) (132096 + ((wm)*5 + (s))*2304)
#define SM_TOT (132096 + 4*5*2304)         // 178176

__global__ __launch_bounds__(256, 1) void lstm_mma_kernel(float* __restrict__ out)
{
    const int tx   = threadIdx.x;
    const int wid  = tx >> 5;
    const int lane = tx & 31;
    const int j    = blockIdx.x;
    const int jj   = j >> 1;
    const int bh   = j & 1;
    const int wm   = wid & 3;
    const int wn   = wid >> 2;
    const uint32_t sb = smem_u32(smem);

    // preload W slice: 64 gate rows (row = q*16 + rem, g = q*1024 + 16jj + rem)
    {
        const __half* Whh = (const __half*)g_WhhH4;
        for (int idx = tx; idx < 64 * 128; idx += 256) {
            int row = idx >> 7, seg = idx & 127;
            int g = ((row >> 4) << 10) + (jj << 4) + (row & 15);
            *(uint4*)(smem + SM_W + row * 2064 + seg * 16) =
                *(const uint4*)(Whh + (size_t)g * HH + seg * 8);
        }
    }

    float c[4] = {0.f, 0.f, 0.f, 0.f};

    const int rowbase = (bh << 6) + (wm << 4);     // CTA-half row base for this warp's tile
    const uint32_t aoff = (uint32_t)((lane & 15) * 144 + ((lane >> 4) << 4));
    // B: row = q*16 + wn*8 + (lane&7); k-offset ((lane>>3)&3)*16B
    const uint32_t wboff = (uint32_t)((wn << 3) * 2064 + (lane & 7) * 2064 + (((lane >> 3) & 3) << 4));
    const uint32_t wb = sb + SM_W + wboff;
    const int barid = 1 + wm;

    const int r0  = lane >> 2;                     // row within 16-row tile
    const int nn0 = (lane & 3) << 1;               // h-subcol within 8
    const int hcol = (jj << 4) + (wn << 3) + nn0;  // global h column base

    const float* xpall = (const float*)g_xproj4;
    __syncthreads();                               // W resident

    for (int t = 0; t < TT; t++) {
        const __half* hcur = (const __half*)g_hbf4[t & 1];

        // x_proj prefetch
        float2 xi[2], xf[2], xg[2], xo[2];
#pragma unroll
        for (int rh = 0; rh < 2; rh++) {
            const int row = rowbase + r0 + (rh << 3);
            const float* bp = xpall + (size_t)t * BB * GG + (size_t)row * GG + hcol;
            xi[rh] = *(const float2*)(bp);
            xf[rh] = *(const float2*)(bp + 1024);
            xg[rh] = *(const float2*)(bp + 2048);
            xo[rh] = *(const float2*)(bp + 3072);
        }

        float acc[4][4];
#pragma unroll
        for (int q = 0; q < 4; q++)
#pragma unroll
            for (int e = 0; e < 4; e++) acc[q][e] = 0.f;

        // prologue: stage k-tiles 0..3; each warp loads its 8 rows of the pair tile
#pragma unroll
        for (int s = 0; s < 4; s++) {
            const int k0 = s << 6;
#pragma unroll
            for (int r = 0; r < 2; r++) {
                int ch = lane + (r << 5);          // 0..63
                int rr = ch >> 3, seg = ch & 7;    // rr 0..7
                CP16(sb + SM_AW(wm, s) + ((wn << 3) + rr) * 144 + seg * 16,
                     hcur + (size_t)(rowbase + (wn << 3) + rr) * HH + k0 + (seg << 3));
            }
            CP_COMMIT();
        }

#pragma unroll 2
        for (int kt = 0; kt < 16; kt++) {
            if (kt < 12) {
                const int k0 = (kt + 4) << 6;
                const int st = (kt + 4) % 5;
#pragma unroll
                for (int r = 0; r < 2; r++) {
                    int ch = lane + (r << 5);
                    int rr = ch >> 3, seg = ch & 7;
                    CP16(sb + SM_AW(wm, st) + ((wn << 3) + rr) * 144 + seg * 16,
                         hcur + (size_t)(rowbase + (wn << 3) + rr) * HH + k0 + (seg << 3));
                }
                CP_COMMIT();
                CP_WAITN(4);
            } else if (kt == 12) CP_WAITN(3);
            else if (kt == 13)   CP_WAITN(2);
            else if (kt == 14)   CP_WAITN(1);
            else                 CP_WAITN(0);
            BARW(barid);                           // pair: both halves of tile kt resident

            const uint32_t aA = sb + SM_AW(wm, kt % 5) + aoff;
#pragma unroll
            for (int ks2 = 0; ks2 < 2; ks2++) {
                uint32_t ah0[4], ah1[4];
                LDSM4(ah0, aA + (ks2 << 6));
                LDSM4(ah1, aA + (ks2 << 6) + 32);
                const uint32_t kcol = (uint32_t)((kt << 7) + (ks2 << 6));
#pragma unroll
                for (int q = 0; q < 4; q++) {
                    uint32_t bhf[4];
                    LDSM4(bhf, wb + q * 33024 + kcol);
                    MMA(acc[q], ah0[0], ah0[1], ah0[2], ah0[3], bhf[0], bhf[1]);
                    MMA(acc[q], ah1[0], ah1[1], ah1[2], ah1[3], bhf[2], bhf[3]);
                }
            }
        }

        // epilogue (register-resident cell update)
        __half* hnext = (__half*)g_hbf4[(t + 1) & 1];
#pragma unroll
        for (int rh = 0; rh < 2; rh++) {
            const int row = rowbase + r0 + (rh << 3);
            float hv[2];
#pragma unroll
            for (int e = 0; e < 2; e++) {
                const int p = (rh << 1) + e;
                float gi = acc[0][p] + (e ? xi[rh].y : xi[rh].x);
                float gf = acc[1][p] + (e ? xf[rh].y : xf[rh].x);
                float gg = acc[2][p] + (e ? xg[rh].y : xg[rh].x);
                float go = acc[3][p] + (e ? xo[rh].y : xo[rh].x);
                float iv = 1.f / (1.f + __expf(-gi));
                float fv = 1.f / (1.f + __expf(-gf));
                float gv = tanhf(gg);
                float ov = 1.f / (1.f + __expf(-go));
                float cv = fv * c[p] + iv * gv;
                c[p] = cv;
                hv[e] = ov * tanhf(cv);
            }
            __half a0 = __float2half_rn(hv[0]);
            __half a1 = __float2half_rn(hv[1]);
            uint32_t ph = (uint32_t)__half_as_ushort(a0) | ((uint32_t)__half_as_ushort(a1) << 16);
            *(uint32_t*)(hnext + row * HH + hcol) = ph;

            if (t == TT - 1) {
                float2 ov2; ov2.x = hv[0]; ov2.y = hv[1];
                *(float2*)(out + row * HH + hcol) = ov2;
            }
        }

        if (t < TT - 1)
            grid_sync_t(bh, jj, t);
    }
}

// ---------------------------------------------------------------------------
extern "C" void kernel_launch(void* const* d_in, const int* in_sizes, int n_in,
                              void* d_out, int out_size)
{
    const float* x   = (const float*)d_in[0];
    const float* Wih = (const float*)d_in[1];
    const float* Whh = (const float*)d_in[2];
    const float* bih = (const float*)d_in[3];
    const float* bhh = (const float*)d_in[4];
    float* out = (float*)d_out;

    cudaFuncSetAttribute(lstm_mma_kernel, cudaFuncAttributeMaxDynamicSharedMemorySize, SM_TOT);
    cudaFuncSetAttribute(xproj_mma,       cudaFuncAttributeMaxDynamicSharedMemorySize, SMX_TOT);

    prep_whh<<<(int)(((size_t)GG * HH + 255) / 256), 256>>>(Whh);
    prep_wih<<<(int)(((size_t)GG * II + 255) / 256), 256>>>(Wih, bih, bhh);
    {
        dim3 g(TT / 32, II / 32, BB);
        dim3 bdim(32, 8);
        prep_x<<<g, bdim>>>(x);
    }
    {
        dim3 g(32, 2, BB);
        xproj_mma<<<g, 256, SMX_TOT>>>();
    }
    lstm_mma_kernel<<<128, 256, SM_TOT>>>(out);
}